// round 1
// baseline (speedup 1.0000x reference)
#include <cuda_runtime.h>
#include <math_constants.h>

#define BB 8
#define CC 256
#define HH 128
#define WW 128
#define HW (HH*WW)
#define TOPK 10
#define THRESH 0.5f
#define MARGIN 0.5f
#define EPSV 1e-8f

// scratch (no allocations allowed)
__device__ float g_intensity[2][BB][HW];   // [0]=det, [1]=loc
__device__ float g_topk_val[2][BB][TOPK];
__device__ int   g_topk_idx[2][BB][TOPK];
__device__ float g_losses[BB];

// ---------------------------------------------------------------------------
// Kernel A: intensity[t][b][p] = sqrt(sum_c f[b][c][p]^2), float4 vectorized.
// 65536 threads, each owns 4 consecutive pixels of one map, loops 256 channels.
// Coalesced 16B loads, unroll 8 for MLP. This kernel carries ~268MB of HBM.
// ---------------------------------------------------------------------------
__global__ void __launch_bounds__(256) intensity_kernel(
    const float* __restrict__ det, const float* __restrict__ loc)
{
    int gid = blockIdx.x * blockDim.x + threadIdx.x;   // 0..65535
    int map = gid >> 12;          // /4096 groups per map
    int g   = gid & 4095;
    int t = map >> 3;             // 0=det, 1=loc
    int b = map & 7;
    const float* src = (t == 0) ? det : loc;
    const float4* base =
        (const float4*)(src + (size_t)b * CC * HW) + g;

    float s0 = 0.f, s1 = 0.f, s2 = 0.f, s3 = 0.f;
    #pragma unroll 8
    for (int c = 0; c < CC; c++) {
        float4 v = base[c * (HW / 4)];
        s0 += v.x * v.x;
        s1 += v.y * v.y;
        s2 += v.z * v.z;
        s3 += v.w * v.w;
    }
    float4 o;
    o.x = sqrtf(s0); o.y = sqrtf(s1); o.z = sqrtf(s2); o.w = sqrtf(s3);
    ((float4*)g_intensity[t][b])[g] = o;
}

// ---------------------------------------------------------------------------
// Kernel B: per map — 3x3 local-max peaks (>THRESH), then top-10 by value
// (ties -> lowest index, matching lax.top_k). One block per map; raw and
// masked intensity both live in dynamic SMEM (2 * 64KB).
// ---------------------------------------------------------------------------
extern __shared__ float sm_dyn[];
__global__ void __launch_bounds__(256) topk_kernel()
{
    float* raw    = sm_dyn;        // HW floats
    float* masked = sm_dyn + HW;   // HW floats
    __shared__ float s_val[256];
    __shared__ int   s_idx[256];

    int t = blockIdx.x >> 3;
    int b = blockIdx.x & 7;
    const float* inten = g_intensity[t][b];

    for (int i = threadIdx.x; i < HW; i += 256) raw[i] = inten[i];
    __syncthreads();

    for (int i = threadIdx.x; i < HW; i += 256) {
        int y = i >> 7, x = i & 127;
        float v = raw[i];
        bool peak = (v > THRESH);
        if (peak) {
            #pragma unroll
            for (int dy = -1; dy <= 1; dy++) {
                int yy = y + dy;
                if (yy < 0 || yy >= HH) continue;
                #pragma unroll
                for (int dx = -1; dx <= 1; dx++) {
                    int xx = x + dx;
                    if (xx < 0 || xx >= WW) continue;
                    if (raw[(yy << 7) + xx] > v) peak = false;
                }
            }
        }
        masked[i] = peak ? v : -CUDART_INF_F;
    }
    __syncthreads();

    for (int k = 0; k < TOPK; k++) {
        float best = -CUDART_INF_F;
        int   besti = 0;
        for (int i = threadIdx.x; i < HW; i += 256) {
            float v = masked[i];
            if (v > best || (v == best && i < besti)) { best = v; besti = i; }
        }
        s_val[threadIdx.x] = best;
        s_idx[threadIdx.x] = besti;
        __syncthreads();
        for (int s = 128; s > 0; s >>= 1) {
            if (threadIdx.x < s) {
                float v2 = s_val[threadIdx.x + s];
                int   i2 = s_idx[threadIdx.x + s];
                if (v2 > s_val[threadIdx.x] ||
                    (v2 == s_val[threadIdx.x] && i2 < s_idx[threadIdx.x])) {
                    s_val[threadIdx.x] = v2;
                    s_idx[threadIdx.x] = i2;
                }
            }
            __syncthreads();
        }
        if (threadIdx.x == 0) {
            g_topk_val[t][b][k] = s_val[0];
            g_topk_idx[t][b][k] = s_idx[0];
            masked[s_idx[0]] = -CUDART_INF_F;
        }
        __syncthreads();
    }
}

// ---------------------------------------------------------------------------
// Kernel C: per sample — gather [TOPK,C] features for det & loc peaks,
// cosine sim (eps-clamped norms), mean of relu(sim - MARGIN) over valid pairs.
// ---------------------------------------------------------------------------
__global__ void __launch_bounds__(256) loss_kernel(
    const float* __restrict__ det, const float* __restrict__ loc)
{
    __shared__ float df[TOPK][CC];
    __shared__ float lf[TOPK][CC];
    __shared__ float na[TOPK], nb[TOPK];
    __shared__ float warp_sum[8];

    int b = blockIdx.x;
    int tid = threadIdx.x;
    int lane = tid & 31, w = tid >> 5;

    // gather: thread = channel, loop peaks
    const size_t base = (size_t)b * CC * HW + (size_t)tid * HW;
    #pragma unroll
    for (int k = 0; k < TOPK; k++) {
        df[k][tid] = det[base + g_topk_idx[0][b][k]];
        lf[k][tid] = loc[base + g_topk_idx[1][b][k]];
    }
    __syncthreads();

    // norms (warp per row)
    for (int k = w; k < TOPK; k += 8) {
        float sa = 0.f, sb = 0.f;
        for (int c = lane; c < CC; c += 32) {
            sa += df[k][c] * df[k][c];
            sb += lf[k][c] * lf[k][c];
        }
        #pragma unroll
        for (int o = 16; o > 0; o >>= 1) {
            sa += __shfl_down_sync(0xffffffffu, sa, o);
            sb += __shfl_down_sync(0xffffffffu, sb, o);
        }
        if (lane == 0) {
            na[k] = fmaxf(sqrtf(sa), EPSV);
            nb[k] = fmaxf(sqrtf(sb), EPSV);
        }
    }
    __syncthreads();

    // 100 pair dots, strided across 8 warps
    float lsum = 0.f;
    for (int p = w; p < TOPK * TOPK; p += 8) {
        int i = p / TOPK, j = p % TOPK;
        bool vd = (g_topk_val[0][b][i] > -CUDART_INF_F);
        bool vl = (g_topk_val[1][b][j] > -CUDART_INF_F);
        float dot = 0.f;
        for (int c = lane; c < CC; c += 32) dot += df[i][c] * lf[j][c];
        #pragma unroll
        for (int o = 16; o > 0; o >>= 1)
            dot += __shfl_down_sync(0xffffffffu, dot, o);
        if (lane == 0 && vd && vl) {
            float sim = dot / (na[i] * nb[j]);
            lsum += fmaxf(sim - MARGIN, 0.f);
        }
    }
    if (lane == 0) warp_sum[w] = lsum;
    __syncthreads();

    if (tid == 0) {
        int nvd = 0, nvl = 0;
        #pragma unroll
        for (int k = 0; k < TOPK; k++) {
            nvd += (g_topk_val[0][b][k] > -CUDART_INF_F) ? 1 : 0;
            nvl += (g_topk_val[1][b][k] > -CUDART_INF_F) ? 1 : 0;
        }
        float s = 0.f;
        #pragma unroll
        for (int ww2 = 0; ww2 < 8; ww2++) s += warp_sum[ww2];
        int n = nvd * nvl;
        g_losses[b] = (n > 0) ? (s / (float)n) : 0.f;
    }
}

// ---------------------------------------------------------------------------
// Kernel D: deterministic fixed-order sum of per-sample losses / B.
// ---------------------------------------------------------------------------
__global__ void finalize_kernel(float* __restrict__ out)
{
    float s = 0.f;
    #pragma unroll
    for (int b = 0; b < BB; b++) s += g_losses[b];
    out[0] = s / (float)BB;
}

extern "C" void kernel_launch(void* const* d_in, const int* in_sizes, int n_in,
                              void* d_out, int out_size)
{
    const float* loc = (const float*)d_in[0];   // loc_features [8,256,128,128]
    const float* det = (const float*)d_in[1];   // det_features [8,256,128,128]
    float* out = (float*)d_out;

    // A: 65536 threads (2*8 maps * 4096 float4 groups)
    intensity_kernel<<<256, 256>>>(det, loc);

    // B: one block per map, 128KB dynamic smem
    cudaFuncSetAttribute(topk_kernel,
                         cudaFuncAttributeMaxDynamicSharedMemorySize,
                         2 * HW * (int)sizeof(float));
    topk_kernel<<<16, 256, 2 * HW * sizeof(float)>>>();

    // C: one block per sample
    loss_kernel<<<BB, 256>>>(det, loc);

    // D: scalar reduce
    finalize_kernel<<<1, 1>>>(out);
}

// round 2
// speedup vs baseline: 1.0411x; 1.0411x over previous
#include <cuda_runtime.h>
#include <math_constants.h>

#define BB 8
#define CC 256
#define HH 128
#define WW 128
#define HW (HH*WW)
#define TOPK 10
#define THRESH 0.5f
#define MARGIN 0.5f
#define EPSV 1e-8f
#define NMAPS 16
#define CAND_CAP 4096   // king-graph max-independent-set bound for 3x3 strict maxima

// scratch (no allocations allowed); counters self-reset -> replay-safe
__device__ float    g_intensity[NMAPS][HW];
__device__ float    g_topk_val[NMAPS][TOPK];
__device__ int      g_topk_idx[NMAPS][TOPK];
__device__ float    g_losses[BB];
__device__ unsigned g_map_cnt[NMAPS];
__device__ unsigned g_samp_cnt[BB];
__device__ unsigned g_done_cnt;

extern __shared__ float smdyn[];

__global__ void __launch_bounds__(256) fused_kernel(
    const float* __restrict__ det, const float* __restrict__ loc,
    float* __restrict__ out)
{
    // dynamic smem layout (96KB): raw[HW] | cval[CAND_CAP] | cidx[CAND_CAP]
    float* raw  = smdyn;
    float* cval = smdyn + HW;
    int*   cidx = (int*)(smdyn + HW + CAND_CAP);
    // loss-phase aliases (raw is dead by then): df[10][256] | lf[10][256]
    float (*df)[CC] = (float(*)[CC])smdyn;
    float (*lf)[CC] = (float(*)[CC])(smdyn + TOPK * CC);

    __shared__ unsigned s_flag;
    __shared__ int s_cn;
    __shared__ float s_na[TOPK], s_nb[TOPK], s_ws[8];

    const int tid = threadIdx.x;
    const int bid = blockIdx.x;      // 0..255
    const int m   = bid >> 4;        // map 0..15  (0..7 det, 8..15 loc)
    const int s   = bid & 15;        // slice within map
    const int t   = m >> 3;
    const int b   = m & 7;

    // ================= Phase A: intensity slice (268MB HBM stream) ==========
    {
        const float* src = (t == 0) ? det : loc;
        const float4* base = ((const float4*)(src + (size_t)b * CC * HW))
                             + (s * 256 + tid);
        float a0 = 0.f, a1 = 0.f, a2 = 0.f, a3 = 0.f;
        #pragma unroll 8
        for (int c = 0; c < CC; c++) {
            float4 v = __ldcs(base + c * (HW / 4));
            a0 = fmaf(v.x, v.x, a0);
            a1 = fmaf(v.y, v.y, a1);
            a2 = fmaf(v.z, v.z, a2);
            a3 = fmaf(v.w, v.w, a3);
        }
        float4 o;
        o.x = sqrtf(a0); o.y = sqrtf(a1); o.z = sqrtf(a2); o.w = sqrtf(a3);
        ((float4*)g_intensity[m])[s * 256 + tid] = o;
    }

    __syncthreads();
    if (tid == 0) {
        __threadfence();
        unsigned old = atomicAdd(&g_map_cnt[m], 1u);
        if (old == 15u) g_map_cnt[m] = 0u;   // reset for next graph replay
        s_flag = (old == 15u);
    }
    __syncthreads();
    if (!s_flag) return;   // only the last block per map continues

    // ================= Phase B: peaks + top-10 for map m =====================
    __threadfence();       // acquire published intensity
    {
        const float* gi = g_intensity[m];
        for (int i = tid; i < HW; i += 256) raw[i] = __ldcg(&gi[i]);
        if (tid == 0) s_cn = 0;
    }
    __syncthreads();

    for (int i = tid; i < HW; i += 256) {
        float v = raw[i];
        if (v > THRESH) {
            int y = i >> 7, x = i & 127;
            bool peak = true;
            #pragma unroll
            for (int dy = -1; dy <= 1; dy++) {
                int yy = y + dy;
                if (yy < 0 || yy >= HH) continue;
                #pragma unroll
                for (int dx = -1; dx <= 1; dx++) {
                    int xx = x + dx;
                    if (xx < 0 || xx >= WW) continue;
                    if (raw[(yy << 7) + xx] > v) peak = false;
                }
            }
            if (peak) {
                int p = atomicAdd(&s_cn, 1);
                if (p < CAND_CAP) { cval[p] = v; cidx[p] = i; }
            }
        }
    }
    __syncthreads();

    // warp 0: 10 argmax passes over ~1.8K candidates (value desc, index asc)
    {
        int n = min(s_cn, CAND_CAP);
        if (tid < 32) {
            for (int k = 0; k < TOPK; k++) {
                float bv = -CUDART_INF_F; int bi = 0x7fffffff; int bp = -1;
                for (int p = tid; p < n; p += 32) {
                    float v = cval[p]; int i = cidx[p];
                    if (v > bv || (v == bv && i < bi)) { bv = v; bi = i; bp = p; }
                }
                #pragma unroll
                for (int o = 16; o > 0; o >>= 1) {
                    float v2 = __shfl_down_sync(0xffffffffu, bv, o);
                    int   i2 = __shfl_down_sync(0xffffffffu, bi, o);
                    int   p2 = __shfl_down_sync(0xffffffffu, bp, o);
                    if (v2 > bv || (v2 == bv && i2 < bi)) { bv = v2; bi = i2; bp = p2; }
                }
                bp = __shfl_sync(0xffffffffu, bp, 0);
                if (tid == 0) {
                    g_topk_val[m][k] = bv;                 // -inf when no candidate
                    g_topk_idx[m][k] = (bp >= 0) ? bi : 0;
                }
                if (bp >= 0 && tid == 0) cval[bp] = -CUDART_INF_F;
                __syncwarp();
            }
        }
    }
    __syncthreads();
    if (tid == 0) {
        __threadfence();
        unsigned old = atomicAdd(&g_samp_cnt[b], 1u);
        if (old == 1u) g_samp_cnt[b] = 0u;   // reset for replay
        s_flag = (old == 1u);
    }
    __syncthreads();
    if (!s_flag) return;   // only 2nd-finished map of this sample continues

    // ================= Phase C: cosine-sim loss for sample b ================
    __threadfence();
    float dkv[TOPK], lkv[TOPK];
    int   dki[TOPK], lki[TOPK];
    #pragma unroll
    for (int k = 0; k < TOPK; k++) {
        dkv[k] = __ldcg(&g_topk_val[b][k]);
        dki[k] = __ldcg(&g_topk_idx[b][k]);
        lkv[k] = __ldcg(&g_topk_val[8 + b][k]);
        lki[k] = __ldcg(&g_topk_idx[8 + b][k]);
    }
    __syncthreads();   // smem reads of raw/cand done before aliasing overwrite

    // gather features: thread = channel
    const size_t cb = (size_t)b * CC * HW + (size_t)tid * HW;
    #pragma unroll
    for (int k = 0; k < TOPK; k++) {
        df[k][tid] = det[cb + dki[k]];
        lf[k][tid] = loc[cb + lki[k]];
    }
    __syncthreads();

    const int lane = tid & 31, w = tid >> 5;
    for (int k = w; k < TOPK; k += 8) {
        float sa = 0.f, sb = 0.f;
        for (int c = lane; c < CC; c += 32) {
            sa = fmaf(df[k][c], df[k][c], sa);
            sb = fmaf(lf[k][c], lf[k][c], sb);
        }
        #pragma unroll
        for (int o = 16; o > 0; o >>= 1) {
            sa += __shfl_down_sync(0xffffffffu, sa, o);
            sb += __shfl_down_sync(0xffffffffu, sb, o);
        }
        if (lane == 0) {
            s_na[k] = fmaxf(sqrtf(sa), EPSV);
            s_nb[k] = fmaxf(sqrtf(sb), EPSV);
        }
    }
    __syncthreads();

    float lsum = 0.f;
    for (int p = w; p < TOPK * TOPK; p += 8) {
        int i = p / TOPK, j = p % TOPK;
        float dot = 0.f;
        for (int c = lane; c < CC; c += 32) dot = fmaf(df[i][c], lf[j][c], dot);
        #pragma unroll
        for (int o = 16; o > 0; o >>= 1)
            dot += __shfl_down_sync(0xffffffffu, dot, o);
        bool vd = (dkv[i] > -CUDART_INF_F);
        bool vl = (lkv[j] > -CUDART_INF_F);
        if (lane == 0 && vd && vl)
            lsum += fmaxf(dot / (s_na[i] * s_nb[j]) - MARGIN, 0.f);
    }
    if (lane == 0) s_ws[w] = lsum;
    __syncthreads();

    if (tid == 0) {
        int nd = 0, nl = 0;
        #pragma unroll
        for (int k = 0; k < TOPK; k++) {
            nd += (dkv[k] > -CUDART_INF_F) ? 1 : 0;
            nl += (lkv[k] > -CUDART_INF_F) ? 1 : 0;
        }
        float ssum = 0.f;
        #pragma unroll
        for (int q = 0; q < 8; q++) ssum += s_ws[q];
        int np = nd * nl;
        g_losses[b] = (np > 0) ? (ssum / (float)np) : 0.f;

        // ============ Phase D: last loss block writes the scalar ============
        __threadfence();
        unsigned old = atomicAdd(&g_done_cnt, 1u);
        if (old == (BB - 1)) {
            g_done_cnt = 0u;   // reset for replay
            __threadfence();
            float tot = 0.f;
            #pragma unroll
            for (int q = 0; q < BB; q++) tot += __ldcg(&g_losses[q]);
            out[0] = tot / (float)BB;
        }
    }
}

extern "C" void kernel_launch(void* const* d_in, const int* in_sizes, int n_in,
                              void* d_out, int out_size)
{
    const float* loc = (const float*)d_in[0];   // loc_features [8,256,128,128]
    const float* det = (const float*)d_in[1];   // det_features [8,256,128,128]
    float* out = (float*)d_out;

    const int smem = (HW + 2 * CAND_CAP) * (int)sizeof(float);   // 96KB
    cudaFuncSetAttribute(fused_kernel,
                         cudaFuncAttributeMaxDynamicSharedMemorySize, smem);
    fused_kernel<<<NMAPS * 16, 256, smem>>>(det, loc, out);
}